// round 14
// baseline (speedup 1.0000x reference)
#include <cuda_runtime.h>
#include <cstdint>

#define BB 128
#define TT 2048
#define NI 128
#define NH 128
#define TILE_T 32
#define N_TILES (TT / TILE_T)   // 64
#define IG_SLOTS 64             // 2 tiles
#define H_SLOTS  64             // 2 tiles

typedef unsigned long long ull;

#define BAR_PROD() asm volatile("bar.sync 1, 128;" ::: "memory")
#define BAR_CONS() asm volatile("bar.sync 2, 128;" ::: "memory")

__device__ __forceinline__ uint32_t tf32hi(float x) {
    uint32_t u;
    asm("cvt.rna.tf32.f32 %0, %1;" : "=r"(u) : "f"(x));
    return u;
}
__device__ __forceinline__ int ld_acquire_shared(const int* p) {
    int v;
    asm volatile("ld.acquire.cta.shared.b32 %0, [%1];"
                 : "=r"(v) : "r"((unsigned)__cvta_generic_to_shared(p)) : "memory");
    return v;
}
__device__ __forceinline__ void st_release_shared(int* p, int v) {
    asm volatile("st.release.cta.shared.b32 [%0], %1;"
                 :: "r"((unsigned)__cvta_generic_to_shared(p)), "r"(v) : "memory");
}

// tf32 mma m16n8k8 (baseline PTX, legal on compute_103)
#define MMA_TF32(c0,c1,c2,c3, a0,a1,a2,a3, b0,b1)                            \
    asm volatile("mma.sync.aligned.m16n8k8.row.col.f32.tf32.tf32.f32 "       \
        "{%0,%1,%2,%3}, {%4,%5,%6,%7}, {%8,%9}, {%0,%1,%2,%3};"              \
        : "+f"(c0), "+f"(c1), "+f"(c2), "+f"(c3)                             \
        : "r"(a0), "r"(a1), "r"(a2), "r"(a3), "r"(b0), "r"(b1))

// ---------------- smem layout (float indices) ----------------
#define WHI_F    0                     // W_in hi fragments (16384 f)
#define WLO_F    16384                 // W_in lo fragments (16384 f)
#define AF_F     32768                 // A tile fragments   (4096 f)
#define IGR_F    36864                 // ig ring [64][128]  (8192 f)
#define HR_F     45056                 // z ring  [64][128]  (8192 f)
#define ROWS_F   53248                 // 0.25*rowsum(W_hh)   (128 f)
#define FLAGS_F  53376                 // [0]=ig tiles, [1]=scan tiles, [2]=copied tiles
#define SMEM_F   53384                 // 213536 B

// ======================================================================
// Fused kernel: 128 CTAs (one per batch) x 256 threads.
//   warps 0-3: PRODUCER — tf32 mma.sync -> ig ring; z->h copy to gmem
//   warps 4-7: CONSUMER — scan matvec on TENSOR pipe (W in A-fragments,
//              z via 32 LDS.32/warp/step) -> 4x less smem crossbar traffic
// ======================================================================
extern __shared__ float g_smem[];

__global__ void __launch_bounds__(256, 1) fused_rnn_kernel(
    const float* __restrict__ inp,      // [B,T,NI]
    const float* __restrict__ hidden0,  // [B,NH]
    const float* __restrict__ W_in,     // [NH,NI]
    const float* __restrict__ b_in,     // [NH]
    const float* __restrict__ W_hh,     // [NH,NH]
    const float* __restrict__ b_hh,     // [NH]
    float* __restrict__ out)            // [B,T,NH]
{
    float* Whi    = g_smem + WHI_F;
    float* Wlo    = g_smem + WLO_F;
    float* AF     = g_smem + AF_F;
    float* igring = g_smem + IGR_F;
    float* hring  = g_smem + HR_F;
    float* rows   = g_smem + ROWS_F;
    int*   flags  = (int*)(g_smem + FLAGS_F);

    const int tid = threadIdx.x;
    const int wid = tid >> 5;
    const int lane = tid & 31;
    const int b = blockIdx.x;

    if (tid == 0) { flags[0] = 0; flags[1] = 0; flags[2] = 0; }

    // ---- 0.25 * rowsum of W_hh (z-form constant) ----
    if (tid < 128) {
        float s = 0.f;
        const float4* wr = (const float4*)(W_hh + (long)tid * NH);
        #pragma unroll
        for (int i = 0; i < 32; i++) {
            float4 v = wr[i];
            s += (v.x + v.y) + (v.z + v.w);
        }
        rows[tid] = 0.25f * s;
    }

    // ---- W_in hi/lo fragment prep (all 256 threads, once) ----
    for (int idx = tid; idx < 128 * 32; idx += 256) {
        int jj = idx >> 5;
        int g4 = idx & 31;
        int k  = g4 * 4;
        float4 v = *(const float4*)(W_in + (long)jj * NI + k);
        float vf[4] = {v.x, v.y, v.z, v.w};
        int nt = jj >> 3, gg = jj & 7, ks = k >> 3;
        int halfk = (k & 7) >= 4 ? 1 : 0;
        #pragma unroll
        for (int e = 0; e < 4; e++) {
            uint32_t hu = tf32hi(vf[e]);
            float hf = __uint_as_float(hu);
            uint32_t lu = tf32hi(vf[e] - hf);
            int fa = ((nt * 16 + ks) * 32 + (gg * 4 + e)) * 2 + halfk;
            Whi[fa] = __uint_as_float(hu);
            Wlo[fa] = __uint_as_float(lu);
        }
    }
    __syncthreads();   // prep + rowsum + flags visible; roles split below

    if (tid < 128) {
        // ============================ PRODUCER ============================
        const float* binp = inp + (long)b * TT * NI;
        float*       outp = out + (long)b * TT * NH;
        const int g  = lane >> 2;      // 0..7
        const int tg = lane & 3;       // 0..3
        const int sID    = wid >> 1;   // m-strip (0..1): rows sID*16..+15
        const int ntbase = (wid & 1) * 8;   // this warp's nt range

        // ring bias: 0.5*(b_in+b_hh)[j] + 0.25*rowsum[j]
        float2 biasf[8];
        #pragma unroll
        for (int ntl = 0; ntl < 8; ntl++) {
            int j0 = (ntbase + ntl) * 8 + tg * 2;
            biasf[ntl].x = 0.5f * (b_in[j0]     + b_hh[j0])     + rows[j0];
            biasf[ntl].y = 0.5f * (b_in[j0 + 1] + b_hh[j0 + 1]) + rows[j0 + 1];
        }

        for (int kt = 0; kt < N_TILES; kt++) {
            const int t0 = kt * TILE_T;

            if (kt >= 2) {
                while (ld_acquire_shared(&flags[1]) < kt - 1) __nanosleep(64);
            }

            // scatter input tile (32 rows) into A-fragment layout
            #pragma unroll
            for (int it = 0; it < 8; it++) {
                int f = tid + it * 128;          // 0..1023 float4 units
                int r = f >> 5;                  // 0..31
                int g4 = f & 31;
                int k = g4 * 4;
                float4 v = __ldcs((const float4*)(binp + (long)(t0 + r) * NI + k));
                float vf[4] = {v.x, v.y, v.z, v.w};
                int w = r >> 4, ks = k >> 3;
                int reg = (((r & 15) >= 8) ? 1 : 0) + (((k & 7) >= 4) ? 2 : 0);
                int baseaddr = ((w * 16 + ks) * 32 + (r & 7) * 4) * 4 + reg;
                #pragma unroll
                for (int e = 0; e < 4; e++)
                    AF[baseaddr + e * 4] = vf[e];
            }
            BAR_PROD();

            // load this warp's strip fragments, split hi/lo
            uint32_t ah[16][4], al[16][4];
            #pragma unroll
            for (int ks = 0; ks < 16; ks++) {
                float4 v = *(const float4*)(AF + ((sID * 16 + ks) * 32 + lane) * 4);
                float vf[4] = {v.x, v.y, v.z, v.w};
                #pragma unroll
                for (int e = 0; e < 4; e++) {
                    ah[ks][e] = tf32hi(vf[e]);
                    al[ks][e] = tf32hi(vf[e] - __uint_as_float(ah[ks][e]));
                }
            }

            // 8 n-tiles x 16 k-steps x 3 mma (3-term tf32)
            #pragma unroll 1
            for (int ntl = 0; ntl < 8; ntl++) {
                int nt = ntbase + ntl;
                float c0 = 0.f, c1 = 0.f, c2 = 0.f, c3 = 0.f;
                const float2* bhp = (const float2*)(Whi + (nt * 16 * 32) * 2) + lane;
                const float2* blp = (const float2*)(Wlo + (nt * 16 * 32) * 2) + lane;
                #pragma unroll
                for (int ks = 0; ks < 16; ks++) {
                    float2 bh = bhp[ks * 32];
                    float2 bl = blp[ks * 32];
                    uint32_t bh0 = __float_as_uint(bh.x), bh1 = __float_as_uint(bh.y);
                    uint32_t bl0 = __float_as_uint(bl.x), bl1 = __float_as_uint(bl.y);
                    MMA_TF32(c0,c1,c2,c3, ah[ks][0],ah[ks][1],ah[ks][2],ah[ks][3], bh0,bh1);
                    MMA_TF32(c0,c1,c2,c3, al[ks][0],al[ks][1],al[ks][2],al[ks][3], bh0,bh1);
                    MMA_TF32(c0,c1,c2,c3, ah[ks][0],ah[ks][1],ah[ks][2],ah[ks][3], bl0,bl1);
                }
                int j0 = nt * 8 + tg * 2;
                int slot0 = (t0 + sID * 16 + g) & (IG_SLOTS - 1);
                int slot1 = (t0 + sID * 16 + g + 8) & (IG_SLOTS - 1);
                *(float2*)(igring + slot0 * NH + j0) =
                    make_float2(fmaf(0.5f, c0, biasf[ntl].x), fmaf(0.5f, c1, biasf[ntl].y));
                *(float2*)(igring + slot1 * NH + j0) =
                    make_float2(fmaf(0.5f, c2, biasf[ntl].x), fmaf(0.5f, c3, biasf[ntl].y));
            }
            BAR_PROD();
            if (tid == 0) st_release_shared(&flags[0], kt + 1);

            // ---- copy z-tile (kt-2) -> h in gmem ----
            if (kt >= 2) {
                int ct = kt - 2;
                #pragma unroll
                for (int it2 = 0; it2 < 8; it2++) {
                    int f = tid + it2 * 128;
                    int r = f >> 5;
                    int c4 = f & 31;
                    int t = ct * TILE_T + r;
                    float4 z4 = *(const float4*)(hring + ((t & (H_SLOTS - 1)) << 7) + c4 * 4);
                    float4 h4 = make_float4(fmaf(0.5f, z4.x, 0.5f), fmaf(0.5f, z4.y, 0.5f),
                                            fmaf(0.5f, z4.z, 0.5f), fmaf(0.5f, z4.w, 0.5f));
                    __stcs((float4*)(outp + (long)t * NH + c4 * 4), h4);
                }
                BAR_PROD();
                if (tid == 0) st_release_shared(&flags[2], kt - 1);
            }
        }

        // tail: copy last two z-tiles
        for (int ct = N_TILES - 2; ct < N_TILES; ct++) {
            while (ld_acquire_shared(&flags[1]) < ct + 1) __nanosleep(64);
            #pragma unroll
            for (int it2 = 0; it2 < 8; it2++) {
                int f = tid + it2 * 128;
                int r = f >> 5;
                int c4 = f & 31;
                int t = ct * TILE_T + r;
                float4 z4 = *(const float4*)(hring + ((t & (H_SLOTS - 1)) << 7) + c4 * 4);
                float4 h4 = make_float4(fmaf(0.5f, z4.x, 0.5f), fmaf(0.5f, z4.y, 0.5f),
                                        fmaf(0.5f, z4.z, 0.5f), fmaf(0.5f, z4.w, 0.5f));
                __stcs((float4*)(outp + (long)t * NH + c4 * 4), h4);
            }
        }
    } else {
        // ============================ CONSUMER ============================
        // warp cw owns j in [cw*32, cw*32+32) as 2 m16 tiles of mma.
        const int cw   = wid - 4;       // 0..3
        const int g    = lane >> 2;     // groupID 0..7
        const int tig  = lane & 3;      // threadID-in-group
        const int jb   = cw * 32;

        // A-fragments: 0.25*W_hh, tf32 RNA-rounded, preloaded once.
        // a0=A[g][tig], a1=A[g+8][tig], a2=A[g][tig+4], a3=A[g+8][tig+4]
        uint32_t af[2][16][4];
        #pragma unroll
        for (int m = 0; m < 2; m++)
            #pragma unroll
            for (int ks = 0; ks < 16; ks++) {
                int r0 = jb + m * 16 + g;
                af[m][ks][0] = tf32hi(0.25f * W_hh[(long)r0 * NH + ks * 8 + tig]);
                af[m][ks][1] = tf32hi(0.25f * W_hh[(long)(r0 + 8) * NH + ks * 8 + tig]);
                af[m][ks][2] = tf32hi(0.25f * W_hh[(long)r0 * NH + ks * 8 + tig + 4]);
                af[m][ks][3] = tf32hi(0.25f * W_hh[(long)(r0 + 8) * NH + ks * 8 + tig + 4]);
            }

        // z_{-1} = 2*h0 - 1 at slot H_SLOTS-1
        if (cw == 0 && lane < 32) { /* warp 4 only seeds with all lanes */ }
        if (wid == 4) {
            // 32 lanes cover 128 j in 4 strided writes
            #pragma unroll
            for (int r = 0; r < 4; r++) {
                int jj = lane + r * 32;
                hring[(H_SLOTS - 1) * NH + jj] =
                    fmaf(2.0f, hidden0[(long)b * NH + jj], -1.0f);
            }
        }

        BAR_CONS();   // z_{-1} visible to all consumer threads

        #pragma unroll 1
        for (int tb = 0; tb < N_TILES; tb++) {
            while (ld_acquire_shared(&flags[0]) < tb + 1) __nanosleep(64);
            if (tb >= 2) {
                while (ld_acquire_shared(&flags[2]) < tb - 1) __nanosleep(64);
            }

            const int t0 = tb * TILE_T;

            #pragma unroll 1
            for (int tt = 0; tt < TILE_T; tt++) {
                const int t = t0 + tt;
                const float* zr = hring + (((t - 1) & (H_SLOTS - 1)) << 7);
                float*       zw = hring + ((t & (H_SLOTS - 1)) << 7);
                const float* igp = igring + ((t & (IG_SLOTS - 1)) << 7);

                // ig for this lane's 4 rows (issued first; only tig==0 uses)
                float ig0 = igp[jb + g];
                float ig1 = igp[jb + g + 8];
                float ig2 = igp[jb + g + 16];
                float ig3 = igp[jb + g + 24];

                // B-fragments: b0[ks] = z[8ks+tig], b1[ks] = z[8ks+4+tig]
                uint32_t b0[16], b1[16];
                #pragma unroll
                for (int ks = 0; ks < 16; ks++) {
                    b0[ks] = __float_as_uint(zr[ks * 8 + tig]);
                    b1[ks] = __float_as_uint(zr[ks * 8 + 4 + tig]);
                }

                // 2 m-tiles x 16 k-steps, 4 accumulator sets (chain depth 4)
                float c[2][4][4];
                #pragma unroll
                for (int m = 0; m < 2; m++)
                    #pragma unroll
                    for (int s = 0; s < 4; s++)
                        #pragma unroll
                        for (int e = 0; e < 4; e++) c[m][s][e] = 0.f;

                #pragma unroll
                for (int ks = 0; ks < 16; ks++) {
                    int s = ks & 3;
                    MMA_TF32(c[0][s][0], c[0][s][1], c[0][s][2], c[0][s][3],
                             af[0][ks][0], af[0][ks][1], af[0][ks][2], af[0][ks][3],
                             b0[ks], b1[ks]);
                    MMA_TF32(c[1][s][0], c[1][s][1], c[1][s][2], c[1][s][3],
                             af[1][ks][0], af[1][ks][1], af[1][ks][2], af[1][ks][3],
                             b0[ks], b1[ks]);
                }

                // combine accumulators (only regs 0 and 2 needed: cols dup)
                float p00 = (c[0][0][0] + c[0][1][0]) + (c[0][2][0] + c[0][3][0]);
                float p01 = (c[0][0][2] + c[0][1][2]) + (c[0][2][2] + c[0][3][2]);
                float p10 = (c[1][0][0] + c[1][1][0]) + (c[1][2][0] + c[1][3][0]);
                float p11 = (c[1][0][2] + c[1][1][2]) + (c[1][2][2] + c[1][3][2]);

                if (tig == 0) {
                    float z0, z1, z2, z3;
                    asm("tanh.approx.f32 %0, %1;" : "=f"(z0) : "f"(p00 + ig0));
                    asm("tanh.approx.f32 %0, %1;" : "=f"(z1) : "f"(p01 + ig1));
                    asm("tanh.approx.f32 %0, %1;" : "=f"(z2) : "f"(p10 + ig2));
                    asm("tanh.approx.f32 %0, %1;" : "=f"(z3) : "f"(p11 + ig3));
                    zw[jb + g]      = z0;
                    zw[jb + g + 8]  = z1;
                    zw[jb + g + 16] = z2;
                    zw[jb + g + 24] = z3;
                }
                BAR_CONS();
            }
            if (tid == 128) st_release_shared(&flags[1], tb + 1);
        }
    }
}

// ======================================================================
extern "C" void kernel_launch(void* const* d_in, const int* in_sizes, int n_in,
                              void* d_out, int out_size)
{
    const float* inp     = (const float*)d_in[0];  // [B,T,NI]
    const float* hidden0 = (const float*)d_in[1];  // [B,NH]
    const float* W_in    = (const float*)d_in[2];  // [NH,NI]
    const float* b_in    = (const float*)d_in[3];  // [NH]
    const float* W_hh    = (const float*)d_in[4];  // [NH,NH]
    const float* b_hh    = (const float*)d_in[5];  // [NH]
    float* out = (float*)d_out;                    // [B,T,NH]

    const int smem_bytes = SMEM_F * 4;   // 213536 B
    cudaFuncSetAttribute(fused_rnn_kernel,
                         cudaFuncAttributeMaxDynamicSharedMemorySize, smem_bytes);

    fused_rnn_kernel<<<BB, 256, smem_bytes>>>(inp, hidden0, W_in, b_in,
                                              W_hh, b_hh, out);
}